// round 9
// baseline (speedup 1.0000x reference)
#include <cuda_runtime.h>

// Problem constants
#define BB 2
#define SS 4096
#define DD 512
#define HH 8
#define DK 64
#define MM (BB * SS)   // 8192 rows
#define QT 128         // q rows per attention block
#define KT 64          // k cols per attention tile

// ---------------------------------------------------------------------------
// Scratch (device globals — no runtime allocation)
// g_Qt / g_Kt are TRANSPOSED per head: [b][h][dk][s]  (dk-major)
// g_V natural: [b][h][s][dk]
// ---------------------------------------------------------------------------
__device__ __align__(16) float g_Qt[BB * HH * DK * SS];
__device__ __align__(16) float g_Kt[BB * HH * DK * SS];
__device__ __align__(16) float g_V [BB * HH * SS * DK];
__device__ __align__(16) float g_att[BB * SS * DD];       // [B,S,D]

// ---------------------------------------------------------------------------
// Packed fp32x2 helpers
// ---------------------------------------------------------------------------
typedef unsigned long long u64;

__device__ __forceinline__ u64 ffma2(u64 a, u64 b, u64 c) {
    u64 d;
    asm("fma.rn.f32x2 %0, %1, %2, %3;" : "=l"(d) : "l"(a), "l"(b), "l"(c));
    return d;
}
__device__ __forceinline__ u64 fmul2(u64 a, u64 b) {
    u64 d;
    asm("mul.rn.f32x2 %0, %1, %2;" : "=l"(d) : "l"(a), "l"(b));
    return d;
}
__device__ __forceinline__ u64 pack2(float x) {
    u64 d;
    asm("mov.b64 %0, {%1, %1};" : "=l"(d) : "f"(x));
    return d;
}
__device__ __forceinline__ u64 packpair(float a, float b) {
    u64 d;
    asm("mov.b64 %0, {%1, %2};" : "=l"(d) : "f"(a), "f"(b));
    return d;
}
__device__ __forceinline__ float2 unpack2(u64 v) {
    float2 r;
    asm("mov.b64 {%0, %1}, %2;" : "=f"(r.x), "=f"(r.y) : "l"(v));
    return r;
}

// ---------------------------------------------------------------------------
// Tiled SGEMM with bias:  C[i,j] = sum_k A[i,k] * W[j,k] + bias[j]
//   A-side staged DUPLICATED as u64 pairs -> zero MOV packs in inner loop.
//   mode 0/1: write TRANSPOSED into g_Qt/g_Kt  ([b][h][dk][s])
//   mode 2  : write natural into g_V           ([b][h][s][dk])
//   mode 3  : A := g_att, plain row-major into Cout
// ---------------------------------------------------------------------------
__global__ __launch_bounds__(256)
void gemm_bias_kernel(const float* __restrict__ A,
                      const float* __restrict__ W,
                      const float* __restrict__ bias,
                      float* __restrict__ Cout,
                      int mode)
{
    __shared__ __align__(16) u64   Asd[16][64];   // duplicated (a,a) pairs
    __shared__ __align__(16) float Bs[16][128];

    const float* Ap = (mode == 3) ? g_att : A;

    const int tid = threadIdx.x;
    const int tx  = tid & 15;
    const int ty  = tid >> 4;
    const int bm  = blockIdx.y;
    const int bn  = blockIdx.x;

    const int lrow = tid >> 2;
    const int lk4  = (tid & 3) << 2;

    const float* Aptr  = Ap + (size_t)(bm * 64 + lrow) * DD + lk4;
    const float* Wptr0 = W  + (size_t)(bn * 128 + lrow) * DD + lk4;
    const float* Wptr1 = Wptr0 + (size_t)64 * DD;

    u64 c[16];
    #pragma unroll
    for (int i = 0; i < 16; i++) c[i] = 0ull;

    for (int kk = 0; kk < DD; kk += 16) {
        float4 a4 = *(const float4*)(Aptr  + kk);
        float4 w0 = *(const float4*)(Wptr0 + kk);
        float4 w1 = *(const float4*)(Wptr1 + kk);
        __syncthreads();
        Asd[lk4 + 0][lrow] = pack2(a4.x);
        Asd[lk4 + 1][lrow] = pack2(a4.y);
        Asd[lk4 + 2][lrow] = pack2(a4.z);
        Asd[lk4 + 3][lrow] = pack2(a4.w);
        Bs[lk4 + 0][lrow] = w0.x;  Bs[lk4 + 1][lrow] = w0.y;
        Bs[lk4 + 2][lrow] = w0.z;  Bs[lk4 + 3][lrow] = w0.w;
        Bs[lk4 + 0][lrow + 64] = w1.x;  Bs[lk4 + 1][lrow + 64] = w1.y;
        Bs[lk4 + 2][lrow + 64] = w1.z;  Bs[lk4 + 3][lrow + 64] = w1.w;
        __syncthreads();

        #pragma unroll
        for (int k = 0; k < 16; k++) {
            const ulonglong2* ap = (const ulonglong2*)&Asd[k][ty << 2];
            ulonglong2 alo = ap[0], ahi = ap[1];
            const u64* bp = (const u64*)&Bs[k][tx << 3];
            u64 b0 = bp[0], b1 = bp[1], b2 = bp[2], b3 = bp[3];
            u64 ax = alo.x, ay = alo.y, az = ahi.x, aw = ahi.y;
            c[0]  = ffma2(ax, b0, c[0]);  c[1]  = ffma2(ax, b1, c[1]);
            c[2]  = ffma2(ax, b2, c[2]);  c[3]  = ffma2(ax, b3, c[3]);
            c[4]  = ffma2(ay, b0, c[4]);  c[5]  = ffma2(ay, b1, c[5]);
            c[6]  = ffma2(ay, b2, c[6]);  c[7]  = ffma2(ay, b3, c[7]);
            c[8]  = ffma2(az, b0, c[8]);  c[9]  = ffma2(az, b1, c[9]);
            c[10] = ffma2(az, b2, c[10]); c[11] = ffma2(az, b3, c[11]);
            c[12] = ffma2(aw, b0, c[12]); c[13] = ffma2(aw, b1, c[13]);
            c[14] = ffma2(aw, b2, c[14]); c[15] = ffma2(aw, b3, c[15]);
        }
    }

    const int r0 = bm * 64 + (ty << 2);
    const int c0 = bn * 128 + (tx << 3);
    float* qkv = (mode == 0) ? g_Qt : (mode == 1) ? g_Kt : g_V;

    #pragma unroll
    for (int i = 0; i < 4; i++) {
        const int row = r0 + i;
        #pragma unroll
        for (int jp = 0; jp < 4; jp++) {
            float2 cv = unpack2(c[i * 4 + jp]);
            const int col0 = c0 + jp * 2;
            float v0 = cv.x + bias[col0];
            float v1 = cv.y + bias[col0 + 1];
            if (mode < 2) {
                const int b  = row >> 12;
                const int s  = row & 4095;
                const int h  = col0 >> 6;
                const int dk = col0 & 63;
                float* base = &qkv[((size_t)(b * HH + h) * DK + dk) * SS + s];
                base[0]  = v0;
                base[SS] = v1;
            } else if (mode == 2) {
                const int b  = row >> 12;
                const int s  = row & 4095;
                const int h  = col0 >> 6;
                const int dk = col0 & 63;
                float* dst = &qkv[(((size_t)(b * HH + h) << 12) + s) * DK + dk];
                dst[0] = v0;  dst[1] = v1;
            } else {
                float* dst = &Cout[(size_t)row * DD + col0];
                dst[0] = v0;  dst[1] = v1;
            }
        }
    }
}

// ---------------------------------------------------------------------------
// Register-tiled causal flash attention — pack-free inner loops.
// Block 256 thr (tx 0..15, ty 0..15). Q-tile 128 rows, K-tile 64 cols.
// K/V staged DUPLICATED as u64 (x,x); P staged PAIRED over row-pairs.
// Inner loops: LDS + FFMA2 only.
// ---------------------------------------------------------------------------
#define QS_STRIDE 132        // floats
#define KD_STRIDE 66         // u64 units (528B, 16B-aligned)
#define SMEM_Q   (64 * QS_STRIDE * 4)            // 33792
#define SMEM_KD  (64 * KD_STRIDE * 8)            // 33792
#define SMEM_ATTN (SMEM_Q + 3 * SMEM_KD)         // 135168

__global__ __launch_bounds__(256, 1)
void attn_kernel()
{
    extern __shared__ char smraw[];
    float* Qs = (float*)smraw;                       // [64][132]  Qs[dk][r]
    u64*   Kd = (u64*)(smraw + SMEM_Q);              // [64][66]   (k,k) dup
    u64*   Vd = (u64*)(smraw + SMEM_Q + SMEM_KD);    // [64][66]   (v,v) dup
    u64*   Pp = (u64*)(smraw + SMEM_Q + 2 * SMEM_KD);// [64][66]   row-pair packed

    const int tid = threadIdx.x;
    const int tx  = tid & 15;
    const int ty  = tid >> 4;
    const int qt  = (SS / QT - 1) - blockIdx.x;   // heaviest first
    const int h   = blockIdx.y;
    const int b   = blockIdx.z;

    const size_t ho_t = (size_t)(b * HH + h) * DK * SS;   // Qt/Kt base
    const size_t ho_v = (size_t)(b * HH + h) * SS * DK;   // V base

    // ---- stage Q tile: 64 dk x 128 rows = 2048 float4 -> 8 iterations ----
    #pragma unroll
    for (int u = 0; u < 8; u++) {
        const int idx = u * 256 + tid;
        const int dk  = idx >> 5;       // 0..63
        const int rg  = idx & 31;       // float4 group 0..31
        float4 v = *(const float4*)(g_Qt + ho_t + (size_t)dk * SS + qt * QT + rg * 4);
        *(float4*)&Qs[dk * QS_STRIDE + rg * 4] = v;
    }

    u64 acc2[4][4];
    #pragma unroll
    for (int i = 0; i < 4; i++)
        #pragma unroll
        for (int j = 0; j < 4; j++) acc2[i][j] = 0ull;

    float m[8], l[8];
    #pragma unroll
    for (int r = 0; r < 8; r++) { m[r] = -1e30f; l[r] = 0.f; }

    const float scale = 0.125f;   // 1/sqrt(64)
    const int ntiles = 2 * qt + 2;

    for (int kt = 0; kt < ntiles; kt++) {
        __syncthreads();
        // ---- stage K/V tiles, duplicated into u64 lanes ----
        #pragma unroll
        for (int u = 0; u < 4; u++) {
            const int idx = u * 256 + tid;
            const int row = idx >> 4;       // 0..63
            const int g4  = idx & 15;       // float4 group 0..15
            float4 kv = *(const float4*)(g_Kt + ho_t + (size_t)row * SS + kt * KT + g4 * 4);
            ulonglong2 klo, khi;
            klo.x = pack2(kv.x);  klo.y = pack2(kv.y);
            khi.x = pack2(kv.z);  khi.y = pack2(kv.w);
            ulonglong2* kdst = (ulonglong2*)(Kd + row * KD_STRIDE + g4 * 4);
            kdst[0] = klo;  kdst[1] = khi;
            float4 vv = *(const float4*)(g_V + ho_v + (size_t)(kt * KT + row) * DK + g4 * 4);
            ulonglong2 vlo, vhi;
            vlo.x = pack2(vv.x);  vlo.y = pack2(vv.y);
            vhi.x = pack2(vv.z);  vhi.y = pack2(vv.w);
            ulonglong2* vdst = (ulonglong2*)(Vd + row * KD_STRIDE + g4 * 4);
            vdst[0] = vlo;  vdst[1] = vhi;
        }
        __syncthreads();

        // ---- QK^T: 8x4 score micro-tile, zero packs ----
        u64 s2[4][4];
        #pragma unroll
        for (int i = 0; i < 4; i++)
            #pragma unroll
            for (int j = 0; j < 4; j++) s2[i][j] = 0ull;

        const float* QsT = Qs + ty * 8;
        const u64*   KdT = Kd + tx * 4;
        #pragma unroll 8
        for (int dk = 0; dk < 64; dk++) {
            const ulonglong2* q2 = (const ulonglong2*)(QsT + dk * QS_STRIDE);
            ulonglong2 qlo = q2[0], qhi = q2[1];
            const ulonglong2* k2 = (const ulonglong2*)(KdT + dk * KD_STRIDE);
            ulonglong2 klo = k2[0], khi = k2[1];
            s2[0][0] = ffma2(qlo.x, klo.x, s2[0][0]);  s2[0][1] = ffma2(qlo.x, klo.y, s2[0][1]);
            s2[0][2] = ffma2(qlo.x, khi.x, s2[0][2]);  s2[0][3] = ffma2(qlo.x, khi.y, s2[0][3]);
            s2[1][0] = ffma2(qlo.y, klo.x, s2[1][0]);  s2[1][1] = ffma2(qlo.y, klo.y, s2[1][1]);
            s2[1][2] = ffma2(qlo.y, khi.x, s2[1][2]);  s2[1][3] = ffma2(qlo.y, khi.y, s2[1][3]);
            s2[2][0] = ffma2(qhi.x, klo.x, s2[2][0]);  s2[2][1] = ffma2(qhi.x, klo.y, s2[2][1]);
            s2[2][2] = ffma2(qhi.x, khi.x, s2[2][2]);  s2[2][3] = ffma2(qhi.x, khi.y, s2[2][3]);
            s2[3][0] = ffma2(qhi.y, klo.x, s2[3][0]);  s2[3][1] = ffma2(qhi.y, klo.y, s2[3][1]);
            s2[3][2] = ffma2(qhi.y, khi.x, s2[3][2]);  s2[3][3] = ffma2(qhi.y, khi.y, s2[3][3]);
        }

        // ---- unpack scores, scale, causal mask ----
        float p[8][4];
        #pragma unroll
        for (int rp = 0; rp < 4; rp++)
            #pragma unroll
            for (int c = 0; c < 4; c++) {
                float2 v = unpack2(s2[rp][c]);
                p[2 * rp][c]     = v.x * scale;
                p[2 * rp + 1][c] = v.y * scale;
            }

        if (kt >= 2 * qt) {   // diagonal tiles only
            const int rbase = qt * QT + ty * 8 - kt * KT;
            #pragma unroll
            for (int r = 0; r < 8; r++) {
                const int lim = rbase + r;
                #pragma unroll
                for (int c = 0; c < 4; c++)
                    if (tx * 4 + c > lim) p[r][c] = -1e30f;
            }
        }

        // ---- online softmax (row reductions over 16 tx lanes) ----
        float cc[8];
        #pragma unroll
        for (int r = 0; r < 8; r++) {
            float mx = fmaxf(fmaxf(p[r][0], p[r][1]), fmaxf(p[r][2], p[r][3]));
            mx = fmaxf(mx, __shfl_xor_sync(0xffffffffu, mx, 1, 16));
            mx = fmaxf(mx, __shfl_xor_sync(0xffffffffu, mx, 2, 16));
            mx = fmaxf(mx, __shfl_xor_sync(0xffffffffu, mx, 4, 16));
            mx = fmaxf(mx, __shfl_xor_sync(0xffffffffu, mx, 8, 16));
            const float mn = fmaxf(m[r], mx);
            cc[r] = __expf(m[r] - mn);
            l[r] *= cc[r];
            m[r] = mn;
        }
        #pragma unroll
        for (int rp = 0; rp < 4; rp++) {
            const u64 ccp = packpair(cc[2 * rp], cc[2 * rp + 1]);
            #pragma unroll
            for (int c = 0; c < 4; c++) acc2[rp][c] = fmul2(acc2[rp][c], ccp);
        }
        #pragma unroll
        for (int r = 0; r < 8; r++) {
            #pragma unroll
            for (int c = 0; c < 4; c++) p[r][c] = __expf(p[r][c] - m[r]);
            float rs = (p[r][0] + p[r][1]) + (p[r][2] + p[r][3]);
            rs += __shfl_xor_sync(0xffffffffu, rs, 1, 16);
            rs += __shfl_xor_sync(0xffffffffu, rs, 2, 16);
            rs += __shfl_xor_sync(0xffffffffu, rs, 4, 16);
            rs += __shfl_xor_sync(0xffffffffu, rs, 8, 16);
            l[r] += rs;
        }

        // ---- write P tile packed over row-pairs (16 packpairs total) ----
        #pragma unroll
        for (int rp = 0; rp < 4; rp++) {
            ulonglong2 w0, w1;
            w0.x = packpair(p[2 * rp][0], p[2 * rp + 1][0]);
            w0.y = packpair(p[2 * rp][1], p[2 * rp + 1][1]);
            w1.x = packpair(p[2 * rp][2], p[2 * rp + 1][2]);
            w1.y = packpair(p[2 * rp][3], p[2 * rp + 1][3]);
            ulonglong2* dst = (ulonglong2*)(Pp + (ty * 4 + rp) * KD_STRIDE + tx * 4);
            dst[0] = w0;  dst[1] = w1;
        }
        __syncthreads();

        // ---- PV: out += P @ V, zero packs ----
        const u64* VdT = Vd + tx * 4;
        const u64* PpT = Pp + (ty * 4) * KD_STRIDE;
        #pragma unroll 4
        for (int j = 0; j < 64; j++) {
            const ulonglong2* v2 = (const ulonglong2*)(VdT + j * KD_STRIDE);
            ulonglong2 vlo = v2[0], vhi = v2[1];
            const u64 pA = PpT[j];
            const u64 pB = PpT[KD_STRIDE + j];
            const u64 pC = PpT[2 * KD_STRIDE + j];
            const u64 pD = PpT[3 * KD_STRIDE + j];
            acc2[0][0] = ffma2(pA, vlo.x, acc2[0][0]);  acc2[0][1] = ffma2(pA, vlo.y, acc2[0][1]);
            acc2[0][2] = ffma2(pA, vhi.x, acc2[0][2]);  acc2[0][3] = ffma2(pA, vhi.y, acc2[0][3]);
            acc2[1][0] = ffma2(pB, vlo.x, acc2[1][0]);  acc2[1][1] = ffma2(pB, vlo.y, acc2[1][1]);
            acc2[1][2] = ffma2(pB, vhi.x, acc2[1][2]);  acc2[1][3] = ffma2(pB, vhi.y, acc2[1][3]);
            acc2[2][0] = ffma2(pC, vlo.x, acc2[2][0]);  acc2[2][1] = ffma2(pC, vlo.y, acc2[2][1]);
            acc2[2][2] = ffma2(pC, vhi.x, acc2[2][2]);  acc2[2][3] = ffma2(pC, vhi.y, acc2[2][3]);
            acc2[3][0] = ffma2(pD, vlo.x, acc2[3][0]);  acc2[3][1] = ffma2(pD, vlo.y, acc2[3][1]);
            acc2[3][2] = ffma2(pD, vhi.x, acc2[3][2]);  acc2[3][3] = ffma2(pD, vhi.y, acc2[3][3]);
        }
    }

    // ---- epilogue: normalize and write ----
    #pragma unroll
    for (int rp = 0; rp < 4; rp++) {
        const float inv0 = 1.f / l[2 * rp];
        const float inv1 = 1.f / l[2 * rp + 1];
        float o0[4], o1[4];
        #pragma unroll
        for (int c = 0; c < 4; c++) {
            float2 v = unpack2(acc2[rp][c]);
            o0[c] = v.x * inv0;
            o1[c] = v.y * inv1;
        }
        const size_t row0 = (size_t)(b * SS + qt * QT + ty * 8 + 2 * rp);
        float* dst0 = g_att + row0 * DD + h * DK + tx * 4;
        *(float4*)dst0        = make_float4(o0[0], o0[1], o0[2], o0[3]);
        *(float4*)(dst0 + DD) = make_float4(o1[0], o1[1], o1[2], o1[3]);
    }
}

// ---------------------------------------------------------------------------
// Launch
// ---------------------------------------------------------------------------
extern "C" void kernel_launch(void* const* d_in, const int* in_sizes, int n_in,
                              void* d_out, int out_size)
{
    const float* x  = (const float*)d_in[0];
    const float* Wq = (const float*)d_in[1];
    const float* bq = (const float*)d_in[2];
    const float* Wk = (const float*)d_in[3];
    const float* bk = (const float*)d_in[4];
    const float* Wv = (const float*)d_in[5];
    const float* bv = (const float*)d_in[6];
    const float* Wo = (const float*)d_in[7];
    const float* bo = (const float*)d_in[8];
    float* out = (float*)d_out;

    dim3 ggrid(DD / 128, MM / 64);   // (4, 128)

    gemm_bias_kernel<<<ggrid, 256>>>(x, Wq, bq, nullptr, 0);
    gemm_bias_kernel<<<ggrid, 256>>>(x, Wk, bk, nullptr, 1);
    gemm_bias_kernel<<<ggrid, 256>>>(x, Wv, bv, nullptr, 2);

    cudaFuncSetAttribute(attn_kernel,
                         cudaFuncAttributeMaxDynamicSharedMemorySize,
                         SMEM_ATTN);
    attn_kernel<<<dim3(SS / QT, HH, BB), 256, SMEM_ATTN>>>();

    gemm_bias_kernel<<<ggrid, 256>>>(nullptr, Wo, bo, out, 3);
}

// round 10
// speedup vs baseline: 1.0587x; 1.0587x over previous
#include <cuda_runtime.h>

// Problem constants
#define BB 2
#define SS 4096
#define DD 512
#define HH 8
#define DK 64
#define MM (BB * SS)   // 8192 rows
#define QT 128         // q rows per attention block
#define KT 64          // k cols per attention tile

// ---------------------------------------------------------------------------
// Scratch (device globals — no runtime allocation)
// g_Qt / g_Kt are TRANSPOSED per head: [b][h][dk][s]  (dk-major)
// g_V natural: [b][h][s][dk]
// ---------------------------------------------------------------------------
__device__ __align__(16) float g_Qt[BB * HH * DK * SS];
__device__ __align__(16) float g_Kt[BB * HH * DK * SS];
__device__ __align__(16) float g_V [BB * HH * SS * DK];
__device__ __align__(16) float g_att[BB * SS * DD];       // [B,S,D]

// ---------------------------------------------------------------------------
// Packed fp32x2 helpers
// ---------------------------------------------------------------------------
typedef unsigned long long u64;

__device__ __forceinline__ u64 ffma2(u64 a, u64 b, u64 c) {
    u64 d;
    asm("fma.rn.f32x2 %0, %1, %2, %3;" : "=l"(d) : "l"(a), "l"(b), "l"(c));
    return d;
}
__device__ __forceinline__ u64 fmul2(u64 a, u64 b) {
    u64 d;
    asm("mul.rn.f32x2 %0, %1, %2;" : "=l"(d) : "l"(a), "l"(b));
    return d;
}
__device__ __forceinline__ u64 pack2(float x) {
    u64 d;
    asm("mov.b64 %0, {%1, %1};" : "=l"(d) : "f"(x));
    return d;
}
__device__ __forceinline__ u64 packpair(float a, float b) {
    u64 d;
    asm("mov.b64 %0, {%1, %2};" : "=l"(d) : "f"(a), "f"(b));
    return d;
}
__device__ __forceinline__ float2 unpack2(u64 v) {
    float2 r;
    asm("mov.b64 {%0, %1}, %2;" : "=f"(r.x), "=f"(r.y) : "l"(v));
    return r;
}

// ---------------------------------------------------------------------------
// Tiled SGEMM with bias:  C[i,j] = sum_k A[i,k] * W[j,k] + bias[j]
//   A-side staged DUPLICATED as u64 pairs -> zero MOV packs in inner loop.
//   mode 0/1: write TRANSPOSED into g_Qt/g_Kt  ([b][h][dk][s])
//   mode 2  : write natural into g_V           ([b][h][s][dk])
//   mode 3  : A := g_att, plain row-major into Cout
// ---------------------------------------------------------------------------
__global__ __launch_bounds__(256)
void gemm_bias_kernel(const float* __restrict__ A,
                      const float* __restrict__ W,
                      const float* __restrict__ bias,
                      float* __restrict__ Cout,
                      int mode)
{
    __shared__ __align__(16) u64   Asd[16][64];   // duplicated (a,a) pairs
    __shared__ __align__(16) float Bs[16][128];

    const float* Ap = (mode == 3) ? g_att : A;

    const int tid = threadIdx.x;
    const int tx  = tid & 15;
    const int ty  = tid >> 4;
    const int bm  = blockIdx.y;
    const int bn  = blockIdx.x;

    const int lrow = tid >> 2;
    const int lk4  = (tid & 3) << 2;

    const float* Aptr  = Ap + (size_t)(bm * 64 + lrow) * DD + lk4;
    const float* Wptr0 = W  + (size_t)(bn * 128 + lrow) * DD + lk4;
    const float* Wptr1 = Wptr0 + (size_t)64 * DD;

    u64 c[16];
    #pragma unroll
    for (int i = 0; i < 16; i++) c[i] = 0ull;

    for (int kk = 0; kk < DD; kk += 16) {
        float4 a4 = *(const float4*)(Aptr  + kk);
        float4 w0 = *(const float4*)(Wptr0 + kk);
        float4 w1 = *(const float4*)(Wptr1 + kk);
        __syncthreads();
        Asd[lk4 + 0][lrow] = pack2(a4.x);
        Asd[lk4 + 1][lrow] = pack2(a4.y);
        Asd[lk4 + 2][lrow] = pack2(a4.z);
        Asd[lk4 + 3][lrow] = pack2(a4.w);
        Bs[lk4 + 0][lrow] = w0.x;  Bs[lk4 + 1][lrow] = w0.y;
        Bs[lk4 + 2][lrow] = w0.z;  Bs[lk4 + 3][lrow] = w0.w;
        Bs[lk4 + 0][lrow + 64] = w1.x;  Bs[lk4 + 1][lrow + 64] = w1.y;
        Bs[lk4 + 2][lrow + 64] = w1.z;  Bs[lk4 + 3][lrow + 64] = w1.w;
        __syncthreads();

        #pragma unroll
        for (int k = 0; k < 16; k++) {
            const ulonglong2* ap = (const ulonglong2*)&Asd[k][ty << 2];
            ulonglong2 alo = ap[0], ahi = ap[1];
            const u64* bp = (const u64*)&Bs[k][tx << 3];
            u64 b0 = bp[0], b1 = bp[1], b2 = bp[2], b3 = bp[3];
            u64 ax = alo.x, ay = alo.y, az = ahi.x, aw = ahi.y;
            c[0]  = ffma2(ax, b0, c[0]);  c[1]  = ffma2(ax, b1, c[1]);
            c[2]  = ffma2(ax, b2, c[2]);  c[3]  = ffma2(ax, b3, c[3]);
            c[4]  = ffma2(ay, b0, c[4]);  c[5]  = ffma2(ay, b1, c[5]);
            c[6]  = ffma2(ay, b2, c[6]);  c[7]  = ffma2(ay, b3, c[7]);
            c[8]  = ffma2(az, b0, c[8]);  c[9]  = ffma2(az, b1, c[9]);
            c[10] = ffma2(az, b2, c[10]); c[11] = ffma2(az, b3, c[11]);
            c[12] = ffma2(aw, b0, c[12]); c[13] = ffma2(aw, b1, c[13]);
            c[14] = ffma2(aw, b2, c[14]); c[15] = ffma2(aw, b3, c[15]);
        }
    }

    const int r0 = bm * 64 + (ty << 2);
    const int c0 = bn * 128 + (tx << 3);
    float* qkv = (mode == 0) ? g_Qt : (mode == 1) ? g_Kt : g_V;

    #pragma unroll
    for (int i = 0; i < 4; i++) {
        const int row = r0 + i;
        #pragma unroll
        for (int jp = 0; jp < 4; jp++) {
            float2 cv = unpack2(c[i * 4 + jp]);
            const int col0 = c0 + jp * 2;
            float v0 = cv.x + bias[col0];
            float v1 = cv.y + bias[col0 + 1];
            if (mode < 2) {
                const int b  = row >> 12;
                const int s  = row & 4095;
                const int h  = col0 >> 6;
                const int dk = col0 & 63;
                float* base = &qkv[((size_t)(b * HH + h) * DK + dk) * SS + s];
                base[0]  = v0;
                base[SS] = v1;
            } else if (mode == 2) {
                const int b  = row >> 12;
                const int s  = row & 4095;
                const int h  = col0 >> 6;
                const int dk = col0 & 63;
                float* dst = &qkv[(((size_t)(b * HH + h) << 12) + s) * DK + dk];
                dst[0] = v0;  dst[1] = v1;
            } else {
                float* dst = &Cout[(size_t)row * DD + col0];
                dst[0] = v0;  dst[1] = v1;
            }
        }
    }
}

// ---------------------------------------------------------------------------
// Register-tiled causal flash attention — pack-free inner loops.
// Block 256 thr (tx 0..15, ty 0..15). Q-tile 128 rows, K-tile 64 cols.
// K/V staged DUPLICATED as u64 (x,x); P staged PAIRED over row-pairs.
// Inner loops: LDS + FFMA2 only.
// ---------------------------------------------------------------------------
#define QS_STRIDE 132        // floats
#define KD_STRIDE 66         // u64 units (528B, 16B-aligned)
#define SMEM_Q   (64 * QS_STRIDE * 4)            // 33792
#define SMEM_KD  (64 * KD_STRIDE * 8)            // 33792
#define SMEM_ATTN (SMEM_Q + 3 * SMEM_KD)         // 135168

__global__ __launch_bounds__(256, 1)
void attn_kernel()
{
    extern __shared__ char smraw[];
    float* Qs = (float*)smraw;                       // [64][132]  Qs[dk][r]
    u64*   Kd = (u64*)(smraw + SMEM_Q);              // [64][66]   (k,k) dup
    u64*   Vd = (u64*)(smraw + SMEM_Q + SMEM_KD);    // [64][66]   (v,v) dup
    u64*   Pp = (u64*)(smraw + SMEM_Q + 2 * SMEM_KD);// [64][66]   row-pair packed

    const int tid = threadIdx.x;
    const int tx  = tid & 15;
    const int ty  = tid >> 4;
    const int qt  = (SS / QT - 1) - blockIdx.x;   // heaviest first
    const int h   = blockIdx.y;
    const int b   = blockIdx.z;

    const size_t ho_t = (size_t)(b * HH + h) * DK * SS;   // Qt/Kt base
    const size_t ho_v = (size_t)(b * HH + h) * SS * DK;   // V base

    // ---- stage Q tile: 64 dk x 128 rows = 2048 float4 -> 8 iterations ----
    #pragma unroll
    for (int u = 0; u < 8; u++) {
        const int idx = u * 256 + tid;
        const int dk  = idx >> 5;       // 0..63
        const int rg  = idx & 31;       // float4 group 0..31
        float4 v = *(const float4*)(g_Qt + ho_t + (size_t)dk * SS + qt * QT + rg * 4);
        *(float4*)&Qs[dk * QS_STRIDE + rg * 4] = v;
    }

    u64 acc2[4][4];
    #pragma unroll
    for (int i = 0; i < 4; i++)
        #pragma unroll
        for (int j = 0; j < 4; j++) acc2[i][j] = 0ull;

    float m[8], l[8];
    #pragma unroll
    for (int r = 0; r < 8; r++) { m[r] = -1e30f; l[r] = 0.f; }

    const float scale = 0.125f;   // 1/sqrt(64)
    const int ntiles = 2 * qt + 2;

    for (int kt = 0; kt < ntiles; kt++) {
        __syncthreads();
        // ---- stage K/V tiles, duplicated into u64 lanes ----
        #pragma unroll
        for (int u = 0; u < 4; u++) {
            const int idx = u * 256 + tid;
            const int row = idx >> 4;       // 0..63
            const int g4  = idx & 15;       // float4 group 0..15
            float4 kv = *(const float4*)(g_Kt + ho_t + (size_t)row * SS + kt * KT + g4 * 4);
            ulonglong2 klo, khi;
            klo.x = pack2(kv.x);  klo.y = pack2(kv.y);
            khi.x = pack2(kv.z);  khi.y = pack2(kv.w);
            ulonglong2* kdst = (ulonglong2*)(Kd + row * KD_STRIDE + g4 * 4);
            kdst[0] = klo;  kdst[1] = khi;
            float4 vv = *(const float4*)(g_V + ho_v + (size_t)(kt * KT + row) * DK + g4 * 4);
            ulonglong2 vlo, vhi;
            vlo.x = pack2(vv.x);  vlo.y = pack2(vv.y);
            vhi.x = pack2(vv.z);  vhi.y = pack2(vv.w);
            ulonglong2* vdst = (ulonglong2*)(Vd + row * KD_STRIDE + g4 * 4);
            vdst[0] = vlo;  vdst[1] = vhi;
        }
        __syncthreads();

        // ---- QK^T: 8x4 score micro-tile, zero packs ----
        u64 s2[4][4];
        #pragma unroll
        for (int i = 0; i < 4; i++)
            #pragma unroll
            for (int j = 0; j < 4; j++) s2[i][j] = 0ull;

        const float* QsT = Qs + ty * 8;
        const u64*   KdT = Kd + tx * 4;
        #pragma unroll 8
        for (int dk = 0; dk < 64; dk++) {
            const ulonglong2* q2 = (const ulonglong2*)(QsT + dk * QS_STRIDE);
            ulonglong2 qlo = q2[0], qhi = q2[1];
            const ulonglong2* k2 = (const ulonglong2*)(KdT + dk * KD_STRIDE);
            ulonglong2 klo = k2[0], khi = k2[1];
            s2[0][0] = ffma2(qlo.x, klo.x, s2[0][0]);  s2[0][1] = ffma2(qlo.x, klo.y, s2[0][1]);
            s2[0][2] = ffma2(qlo.x, khi.x, s2[0][2]);  s2[0][3] = ffma2(qlo.x, khi.y, s2[0][3]);
            s2[1][0] = ffma2(qlo.y, klo.x, s2[1][0]);  s2[1][1] = ffma2(qlo.y, klo.y, s2[1][1]);
            s2[1][2] = ffma2(qlo.y, khi.x, s2[1][2]);  s2[1][3] = ffma2(qlo.y, khi.y, s2[1][3]);
            s2[2][0] = ffma2(qhi.x, klo.x, s2[2][0]);  s2[2][1] = ffma2(qhi.x, klo.y, s2[2][1]);
            s2[2][2] = ffma2(qhi.x, khi.x, s2[2][2]);  s2[2][3] = ffma2(qhi.x, khi.y, s2[2][3]);
            s2[3][0] = ffma2(qhi.y, klo.x, s2[3][0]);  s2[3][1] = ffma2(qhi.y, klo.y, s2[3][1]);
            s2[3][2] = ffma2(qhi.y, khi.x, s2[3][2]);  s2[3][3] = ffma2(qhi.y, khi.y, s2[3][3]);
        }

        // ---- unpack scores, scale, causal mask ----
        float p[8][4];
        #pragma unroll
        for (int rp = 0; rp < 4; rp++)
            #pragma unroll
            for (int c = 0; c < 4; c++) {
                float2 v = unpack2(s2[rp][c]);
                p[2 * rp][c]     = v.x * scale;
                p[2 * rp + 1][c] = v.y * scale;
            }

        if (kt >= 2 * qt) {   // diagonal tiles only
            const int rbase = qt * QT + ty * 8 - kt * KT;
            #pragma unroll
            for (int r = 0; r < 8; r++) {
                const int lim = rbase + r;
                #pragma unroll
                for (int c = 0; c < 4; c++)
                    if (tx * 4 + c > lim) p[r][c] = -1e30f;
            }
        }

        // ---- online softmax (row reductions over 16 tx lanes) ----
        float cc[8];
        #pragma unroll
        for (int r = 0; r < 8; r++) {
            float mx = fmaxf(fmaxf(p[r][0], p[r][1]), fmaxf(p[r][2], p[r][3]));
            mx = fmaxf(mx, __shfl_xor_sync(0xffffffffu, mx, 1, 16));
            mx = fmaxf(mx, __shfl_xor_sync(0xffffffffu, mx, 2, 16));
            mx = fmaxf(mx, __shfl_xor_sync(0xffffffffu, mx, 4, 16));
            mx = fmaxf(mx, __shfl_xor_sync(0xffffffffu, mx, 8, 16));
            const float mn = fmaxf(m[r], mx);
            cc[r] = __expf(m[r] - mn);
            l[r] *= cc[r];
            m[r] = mn;
        }
        #pragma unroll
        for (int rp = 0; rp < 4; rp++) {
            const u64 ccp = packpair(cc[2 * rp], cc[2 * rp + 1]);
            #pragma unroll
            for (int c = 0; c < 4; c++) acc2[rp][c] = fmul2(acc2[rp][c], ccp);
        }
        #pragma unroll
        for (int r = 0; r < 8; r++) {
            #pragma unroll
            for (int c = 0; c < 4; c++) p[r][c] = __expf(p[r][c] - m[r]);
            float rs = (p[r][0] + p[r][1]) + (p[r][2] + p[r][3]);
            rs += __shfl_xor_sync(0xffffffffu, rs, 1, 16);
            rs += __shfl_xor_sync(0xffffffffu, rs, 2, 16);
            rs += __shfl_xor_sync(0xffffffffu, rs, 4, 16);
            rs += __shfl_xor_sync(0xffffffffu, rs, 8, 16);
            l[r] += rs;
        }

        // ---- write P tile packed over row-pairs (16 packpairs total) ----
        #pragma unroll
        for (int rp = 0; rp < 4; rp++) {
            ulonglong2 w0, w1;
            w0.x = packpair(p[2 * rp][0], p[2 * rp + 1][0]);
            w0.y = packpair(p[2 * rp][1], p[2 * rp + 1][1]);
            w1.x = packpair(p[2 * rp][2], p[2 * rp + 1][2]);
            w1.y = packpair(p[2 * rp][3], p[2 * rp + 1][3]);
            ulonglong2* dst = (ulonglong2*)(Pp + (ty * 4 + rp) * KD_STRIDE + tx * 4);
            dst[0] = w0;  dst[1] = w1;
        }
        __syncthreads();

        // ---- PV: out += P @ V, zero packs ----
        const u64* VdT = Vd + tx * 4;
        const u64* PpT = Pp + (ty * 4) * KD_STRIDE;
        #pragma unroll 4
        for (int j = 0; j < 64; j++) {
            const ulonglong2* v2 = (const ulonglong2*)(VdT + j * KD_STRIDE);
            ulonglong2 vlo = v2[0], vhi = v2[1];
            const u64 pA = PpT[j];
            const u64 pB = PpT[KD_STRIDE + j];
            const u64 pC = PpT[2 * KD_STRIDE + j];
            const u64 pD = PpT[3 * KD_STRIDE + j];
            acc2[0][0] = ffma2(pA, vlo.x, acc2[0][0]);  acc2[0][1] = ffma2(pA, vlo.y, acc2[0][1]);
            acc2[0][2] = ffma2(pA, vhi.x, acc2[0][2]);  acc2[0][3] = ffma2(pA, vhi.y, acc2[0][3]);
            acc2[1][0] = ffma2(pB, vlo.x, acc2[1][0]);  acc2[1][1] = ffma2(pB, vlo.y, acc2[1][1]);
            acc2[1][2] = ffma2(pB, vhi.x, acc2[1][2]);  acc2[1][3] = ffma2(pB, vhi.y, acc2[1][3]);
            acc2[2][0] = ffma2(pC, vlo.x, acc2[2][0]);  acc2[2][1] = ffma2(pC, vlo.y, acc2[2][1]);
            acc2[2][2] = ffma2(pC, vhi.x, acc2[2][2]);  acc2[2][3] = ffma2(pC, vhi.y, acc2[2][3]);
            acc2[3][0] = ffma2(pD, vlo.x, acc2[3][0]);  acc2[3][1] = ffma2(pD, vlo.y, acc2[3][1]);
            acc2[3][2] = ffma2(pD, vhi.x, acc2[3][2]);  acc2[3][3] = ffma2(pD, vhi.y, acc2[3][3]);
        }
    }

    // ---- epilogue: normalize and write ----
    #pragma unroll
    for (int rp = 0; rp < 4; rp++) {
        const float inv0 = 1.f / l[2 * rp];
        const float inv1 = 1.f / l[2 * rp + 1];
        float o0[4], o1[4];
        #pragma unroll
        for (int c = 0; c < 4; c++) {
            float2 v = unpack2(acc2[rp][c]);
            o0[c] = v.x * inv0;
            o1[c] = v.y * inv1;
        }
        const size_t row0 = (size_t)(b * SS + qt * QT + ty * 8 + 2 * rp);
        float* dst0 = g_att + row0 * DD + h * DK + tx * 4;
        *(float4*)dst0        = make_float4(o0[0], o0[1], o0[2], o0[3]);
        *(float4*)(dst0 + DD) = make_float4(o1[0], o1[1], o1[2], o1[3]);
    }
}

// ---------------------------------------------------------------------------
// Launch
// ---------------------------------------------------------------------------
extern "C" void kernel_launch(void* const* d_in, const int* in_sizes, int n_in,
                              void* d_out, int out_size)
{
    const float* x  = (const float*)d_in[0];
    const float* Wq = (const float*)d_in[1];
    const float* bq = (const float*)d_in[2];
    const float* Wk = (const float*)d_in[3];
    const float* bk = (const float*)d_in[4];
    const float* Wv = (const float*)d_in[5];
    const float* bv = (const float*)d_in[6];
    const float* Wo = (const float*)d_in[7];
    const float* bo = (const float*)d_in[8];
    float* out = (float*)d_out;

    dim3 ggrid(DD / 128, MM / 64);   // (4, 128)

    gemm_bias_kernel<<<ggrid, 256>>>(x, Wq, bq, nullptr, 0);
    gemm_bias_kernel<<<ggrid, 256>>>(x, Wk, bk, nullptr, 1);
    gemm_bias_kernel<<<ggrid, 256>>>(x, Wv, bv, nullptr, 2);

    cudaFuncSetAttribute(attn_kernel,
                         cudaFuncAttributeMaxDynamicSharedMemorySize,
                         SMEM_ATTN);
    attn_kernel<<<dim3(SS / QT, HH, BB), 256, SMEM_ATTN>>>();

    gemm_bias_kernel<<<ggrid, 256>>>(nullptr, Wo, bo, out, 3);
}

// round 11
// speedup vs baseline: 1.4583x; 1.3774x over previous
#include <cuda_runtime.h>

// Problem constants
#define BB 2
#define SS 4096
#define DD 512
#define HH 8
#define DK 64
#define MM (BB * SS)   // 8192 rows
#define QT 128         // q rows per attention block
#define KT 64          // k cols per attention tile

// ---------------------------------------------------------------------------
// Scratch (device globals — no runtime allocation)
// g_Qt / g_Kt are TRANSPOSED per head: [b][h][dk][s]  (dk-major)
// g_V natural: [b][h][s][dk]
// ---------------------------------------------------------------------------
__device__ __align__(16) float g_Qt[BB * HH * DK * SS];
__device__ __align__(16) float g_Kt[BB * HH * DK * SS];
__device__ __align__(16) float g_V [BB * HH * SS * DK];
__device__ __align__(16) float g_att[BB * SS * DD];       // [B,S,D]

// ---------------------------------------------------------------------------
// Packed fp32x2 helpers
// ---------------------------------------------------------------------------
typedef unsigned long long u64;

__device__ __forceinline__ u64 ffma2(u64 a, u64 b, u64 c) {
    u64 d;
    asm("fma.rn.f32x2 %0, %1, %2, %3;" : "=l"(d) : "l"(a), "l"(b), "l"(c));
    return d;
}
__device__ __forceinline__ u64 fmul2(u64 a, u64 b) {
    u64 d;
    asm("mul.rn.f32x2 %0, %1, %2;" : "=l"(d) : "l"(a), "l"(b));
    return d;
}
__device__ __forceinline__ u64 pack2(float x) {
    u64 d;
    asm("mov.b64 %0, {%1, %1};" : "=l"(d) : "f"(x));
    return d;
}
__device__ __forceinline__ u64 packpair(float a, float b) {
    u64 d;
    asm("mov.b64 %0, {%1, %2};" : "=l"(d) : "f"(a), "f"(b));
    return d;
}
__device__ __forceinline__ float2 unpack2(u64 v) {
    float2 r;
    asm("mov.b64 {%0, %1}, %2;" : "=f"(r.x), "=f"(r.y) : "l"(v));
    return r;
}

// ---------------------------------------------------------------------------
// Tiled SGEMM with bias (R8-proven form):
//   C[i,j] = sum_k A[i,k] * W[j,k] + bias[j]
//   mode 0/1: write TRANSPOSED into g_Qt/g_Kt  ([b][h][dk][s])
//   mode 2  : write natural into g_V           ([b][h][s][dk])
//   mode 3  : A := g_att, plain row-major into Cout
// ---------------------------------------------------------------------------
__global__ __launch_bounds__(256)
void gemm_bias_kernel(const float* __restrict__ A,
                      const float* __restrict__ W,
                      const float* __restrict__ bias,
                      float* __restrict__ Cout,
                      int mode)
{
    __shared__ __align__(16) float As[16][64];
    __shared__ __align__(16) float Bs[16][128];

    const float* Ap = (mode == 3) ? g_att : A;

    const int tid = threadIdx.x;
    const int tx  = tid & 15;
    const int ty  = tid >> 4;
    const int bm  = blockIdx.y;
    const int bn  = blockIdx.x;

    const int lrow = tid >> 2;
    const int lk4  = (tid & 3) << 2;

    const float* Aptr  = Ap + (size_t)(bm * 64 + lrow) * DD + lk4;
    const float* Wptr0 = W  + (size_t)(bn * 128 + lrow) * DD + lk4;
    const float* Wptr1 = Wptr0 + (size_t)64 * DD;

    u64 c[16];
    #pragma unroll
    for (int i = 0; i < 16; i++) c[i] = 0ull;

    for (int kk = 0; kk < DD; kk += 16) {
        float4 a4 = *(const float4*)(Aptr  + kk);
        float4 w0 = *(const float4*)(Wptr0 + kk);
        float4 w1 = *(const float4*)(Wptr1 + kk);
        __syncthreads();
        As[lk4 + 0][lrow] = a4.x;  As[lk4 + 1][lrow] = a4.y;
        As[lk4 + 2][lrow] = a4.z;  As[lk4 + 3][lrow] = a4.w;
        Bs[lk4 + 0][lrow] = w0.x;  Bs[lk4 + 1][lrow] = w0.y;
        Bs[lk4 + 2][lrow] = w0.z;  Bs[lk4 + 3][lrow] = w0.w;
        Bs[lk4 + 0][lrow + 64] = w1.x;  Bs[lk4 + 1][lrow + 64] = w1.y;
        Bs[lk4 + 2][lrow + 64] = w1.z;  Bs[lk4 + 3][lrow + 64] = w1.w;
        __syncthreads();

        #pragma unroll
        for (int k = 0; k < 16; k++) {
            float4 av = *(const float4*)&As[k][ty << 2];
            const u64* bp = (const u64*)&Bs[k][tx << 3];
            u64 b0 = bp[0], b1 = bp[1], b2 = bp[2], b3 = bp[3];
            u64 ax = pack2(av.x), ay = pack2(av.y);
            u64 az = pack2(av.z), aw = pack2(av.w);
            c[0]  = ffma2(ax, b0, c[0]);  c[1]  = ffma2(ax, b1, c[1]);
            c[2]  = ffma2(ax, b2, c[2]);  c[3]  = ffma2(ax, b3, c[3]);
            c[4]  = ffma2(ay, b0, c[4]);  c[5]  = ffma2(ay, b1, c[5]);
            c[6]  = ffma2(ay, b2, c[6]);  c[7]  = ffma2(ay, b3, c[7]);
            c[8]  = ffma2(az, b0, c[8]);  c[9]  = ffma2(az, b1, c[9]);
            c[10] = ffma2(az, b2, c[10]); c[11] = ffma2(az, b3, c[11]);
            c[12] = ffma2(aw, b0, c[12]); c[13] = ffma2(aw, b1, c[13]);
            c[14] = ffma2(aw, b2, c[14]); c[15] = ffma2(aw, b3, c[15]);
        }
    }

    const int r0 = bm * 64 + (ty << 2);
    const int c0 = bn * 128 + (tx << 3);
    float* qkv = (mode == 0) ? g_Qt : (mode == 1) ? g_Kt : g_V;

    #pragma unroll
    for (int i = 0; i < 4; i++) {
        const int row = r0 + i;
        #pragma unroll
        for (int jp = 0; jp < 4; jp++) {
            float2 cv = unpack2(c[i * 4 + jp]);
            const int col0 = c0 + jp * 2;
            float v0 = cv.x + bias[col0];
            float v1 = cv.y + bias[col0 + 1];
            if (mode < 2) {
                const int b  = row >> 12;
                const int s  = row & 4095;
                const int h  = col0 >> 6;
                const int dk = col0 & 63;
                float* base = &qkv[((size_t)(b * HH + h) * DK + dk) * SS + s];
                base[0]  = v0;
                base[SS] = v1;
            } else if (mode == 2) {
                const int b  = row >> 12;
                const int s  = row & 4095;
                const int h  = col0 >> 6;
                const int dk = col0 & 63;
                float* dst = &qkv[(((size_t)(b * HH + h) << 12) + s) * DK + dk];
                dst[0] = v0;  dst[1] = v1;
            } else {
                float* dst = &Cout[(size_t)row * DD + col0];
                dst[0] = v0;  dst[1] = v1;
            }
        }
    }
}

// ---------------------------------------------------------------------------
// Register-tiled causal flash attention, 8x8 micro-tile.
// Block 128 thr: tx 0..7 (8 keys / 8 dk-cols each), ty 0..15 (8 q rows each).
// QK: 4 LDS + 8 MOV per 32 FFMA2. PV: 4 LDS + 8 MOV per 32 FFMA2.
// P written row-pair packed; P-write -> PV-read is same-warp (syncwarp).
// ---------------------------------------------------------------------------
#define QS_STRIDE 132        // floats
#define KS_STRIDE 68         // floats
#define PP_STRIDE 66         // u64
#define SMEM_Q   (64 * QS_STRIDE * 4)   // 33792
#define SMEM_K   (64 * KS_STRIDE * 4)   // 17408
#define SMEM_V   (64 * KS_STRIDE * 4)   // 17408
#define SMEM_P   (64 * PP_STRIDE * 8)   // 33792
#define SMEM_ATTN (SMEM_Q + SMEM_K + SMEM_V + SMEM_P)   // 102400

__global__ __launch_bounds__(128)
void attn_kernel()
{
    extern __shared__ char smraw[];
    float* Qs = (float*)smraw;                           // [64 dk][132]  Qs[dk][row]
    float* Ks = (float*)(smraw + SMEM_Q);                // [64 dk][68]   Ks[dk][key]
    float* Vs = (float*)(smraw + SMEM_Q + SMEM_K);       // [64 key][68]  Vs[key][dk]
    u64*   Pp = (u64*)(smraw + SMEM_Q + SMEM_K + SMEM_V);// [64 rowpair][66]

    const int tid = threadIdx.x;
    const int tx  = tid & 7;          // 8 cols of 8
    const int ty  = tid >> 3;         // 16 rows of 8
    const int qt  = (SS / QT - 1) - blockIdx.x;   // heaviest first
    const int h   = blockIdx.y;
    const int b   = blockIdx.z;

    const size_t ho_t = (size_t)(b * HH + h) * DK * SS;   // Qt/Kt base
    const size_t ho_v = (size_t)(b * HH + h) * SS * DK;   // V base

    // ---- stage Q tile: 64 dk x 128 rows = 2048 float4 over 128 thr ----
    #pragma unroll
    for (int u = 0; u < 16; u++) {
        const int idx = u * 128 + tid;
        const int dk  = idx >> 5;       // 0..63
        const int rg  = idx & 31;       // float4 group 0..31
        float4 v = *(const float4*)(g_Qt + ho_t + (size_t)dk * SS + qt * QT + rg * 4);
        *(float4*)&Qs[dk * QS_STRIDE + rg * 4] = v;
    }

    u64 acc2[4][8];
    #pragma unroll
    for (int i = 0; i < 4; i++)
        #pragma unroll
        for (int j = 0; j < 8; j++) acc2[i][j] = 0ull;

    float m[8], l[8];
    #pragma unroll
    for (int r = 0; r < 8; r++) { m[r] = -1e30f; l[r] = 0.f; }

    const float scale = 0.125f;   // 1/sqrt(64)
    const int ntiles = 2 * qt + 2;

    for (int kt = 0; kt < ntiles; kt++) {
        __syncthreads();
        // ---- stage K (dk-major) and V (key-major) tiles ----
        #pragma unroll
        for (int u = 0; u < 8; u++) {
            const int idx = u * 128 + tid;
            const int row = idx >> 4;       // 0..63
            const int g4  = idx & 15;       // float4 group 0..15
            float4 kv = *(const float4*)(g_Kt + ho_t + (size_t)row * SS + kt * KT + g4 * 4);
            *(float4*)&Ks[row * KS_STRIDE + g4 * 4] = kv;
            float4 vv = *(const float4*)(g_V + ho_v + (size_t)(kt * KT + row) * DK + g4 * 4);
            *(float4*)&Vs[row * KS_STRIDE + g4 * 4] = vv;
        }
        __syncthreads();

        // ---- QK^T: 8x8 score micro-tile ----
        u64 s2[4][8];
        #pragma unroll
        for (int i = 0; i < 4; i++)
            #pragma unroll
            for (int j = 0; j < 8; j++) s2[i][j] = 0ull;

        const float* QsT = Qs + ty * 8;
        const float* KsT = Ks + tx * 8;
        #pragma unroll 4
        for (int dk = 0; dk < 64; dk++) {
            ulonglong2 qlo = *(const ulonglong2*)(QsT + dk * QS_STRIDE);
            ulonglong2 qhi = *(const ulonglong2*)(QsT + dk * QS_STRIDE + 4);
            float4 ka = *(const float4*)(KsT + dk * KS_STRIDE);
            float4 kb = *(const float4*)(KsT + dk * KS_STRIDE + 4);
            const u64 k0 = pack2(ka.x), k1 = pack2(ka.y), k2 = pack2(ka.z), k3 = pack2(ka.w);
            const u64 k4 = pack2(kb.x), k5 = pack2(kb.y), k6 = pack2(kb.z), k7 = pack2(kb.w);
            s2[0][0] = ffma2(qlo.x, k0, s2[0][0]);  s2[0][1] = ffma2(qlo.x, k1, s2[0][1]);
            s2[0][2] = ffma2(qlo.x, k2, s2[0][2]);  s2[0][3] = ffma2(qlo.x, k3, s2[0][3]);
            s2[0][4] = ffma2(qlo.x, k4, s2[0][4]);  s2[0][5] = ffma2(qlo.x, k5, s2[0][5]);
            s2[0][6] = ffma2(qlo.x, k6, s2[0][6]);  s2[0][7] = ffma2(qlo.x, k7, s2[0][7]);
            s2[1][0] = ffma2(qlo.y, k0, s2[1][0]);  s2[1][1] = ffma2(qlo.y, k1, s2[1][1]);
            s2[1][2] = ffma2(qlo.y, k2, s2[1][2]);  s2[1][3] = ffma2(qlo.y, k3, s2[1][3]);
            s2[1][4] = ffma2(qlo.y, k4, s2[1][4]);  s2[1][5] = ffma2(qlo.y, k5, s2[1][5]);
            s2[1][6] = ffma2(qlo.y, k6, s2[1][6]);  s2[1][7] = ffma2(qlo.y, k7, s2[1][7]);
            s2[2][0] = ffma2(qhi.x, k0, s2[2][0]);  s2[2][1] = ffma2(qhi.x, k1, s2[2][1]);
            s2[2][2] = ffma2(qhi.x, k2, s2[2][2]);  s2[2][3] = ffma2(qhi.x, k3, s2[2][3]);
            s2[2][4] = ffma2(qhi.x, k4, s2[2][4]);  s2[2][5] = ffma2(qhi.x, k5, s2[2][5]);
            s2[2][6] = ffma2(qhi.x, k6, s2[2][6]);  s2[2][7] = ffma2(qhi.x, k7, s2[2][7]);
            s2[3][0] = ffma2(qhi.y, k0, s2[3][0]);  s2[3][1] = ffma2(qhi.y, k1, s2[3][1]);
            s2[3][2] = ffma2(qhi.y, k2, s2[3][2]);  s2[3][3] = ffma2(qhi.y, k3, s2[3][3]);
            s2[3][4] = ffma2(qhi.y, k4, s2[3][4]);  s2[3][5] = ffma2(qhi.y, k5, s2[3][5]);
            s2[3][6] = ffma2(qhi.y, k6, s2[3][6]);  s2[3][7] = ffma2(qhi.y, k7, s2[3][7]);
        }

        // ---- unpack scores, scale, causal mask ----
        float p[8][8];
        #pragma unroll
        for (int rp = 0; rp < 4; rp++)
            #pragma unroll
            for (int c = 0; c < 8; c++) {
                float2 v = unpack2(s2[rp][c]);
                p[2 * rp][c]     = v.x * scale;
                p[2 * rp + 1][c] = v.y * scale;
            }

        if (kt >= 2 * qt) {   // diagonal tiles only
            const int rbase = qt * QT + ty * 8 - kt * KT;
            #pragma unroll
            for (int r = 0; r < 8; r++) {
                const int lim = rbase + r;
                #pragma unroll
                for (int c = 0; c < 8; c++)
                    if (tx * 8 + c > lim) p[r][c] = -1e30f;
            }
        }

        // ---- online softmax (row reductions over 8 tx lanes) ----
        float cc[8];
        #pragma unroll
        for (int r = 0; r < 8; r++) {
            float mx = fmaxf(fmaxf(fmaxf(p[r][0], p[r][1]), fmaxf(p[r][2], p[r][3])),
                             fmaxf(fmaxf(p[r][4], p[r][5]), fmaxf(p[r][6], p[r][7])));
            mx = fmaxf(mx, __shfl_xor_sync(0xffffffffu, mx, 1, 8));
            mx = fmaxf(mx, __shfl_xor_sync(0xffffffffu, mx, 2, 8));
            mx = fmaxf(mx, __shfl_xor_sync(0xffffffffu, mx, 4, 8));
            const float mn = fmaxf(m[r], mx);
            cc[r] = __expf(m[r] - mn);
            l[r] *= cc[r];
            m[r] = mn;
        }
        #pragma unroll
        for (int rp = 0; rp < 4; rp++) {
            const u64 ccp = packpair(cc[2 * rp], cc[2 * rp + 1]);
            #pragma unroll
            for (int c = 0; c < 8; c++) acc2[rp][c] = fmul2(acc2[rp][c], ccp);
        }
        #pragma unroll
        for (int r = 0; r < 8; r++) {
            #pragma unroll
            for (int c = 0; c < 8; c++) p[r][c] = __expf(p[r][c] - m[r]);
            float rs = ((p[r][0] + p[r][1]) + (p[r][2] + p[r][3]))
                     + ((p[r][4] + p[r][5]) + (p[r][6] + p[r][7]));
            rs += __shfl_xor_sync(0xffffffffu, rs, 1, 8);
            rs += __shfl_xor_sync(0xffffffffu, rs, 2, 8);
            rs += __shfl_xor_sync(0xffffffffu, rs, 4, 8);
            l[r] += rs;
        }

        // ---- write P tile packed over row-pairs ----
        #pragma unroll
        for (int rp = 0; rp < 4; rp++) {
            ulonglong2 w0, w1, w2, w3;
            w0.x = packpair(p[2 * rp][0], p[2 * rp + 1][0]);
            w0.y = packpair(p[2 * rp][1], p[2 * rp + 1][1]);
            w1.x = packpair(p[2 * rp][2], p[2 * rp + 1][2]);
            w1.y = packpair(p[2 * rp][3], p[2 * rp + 1][3]);
            w2.x = packpair(p[2 * rp][4], p[2 * rp + 1][4]);
            w2.y = packpair(p[2 * rp][5], p[2 * rp + 1][5]);
            w3.x = packpair(p[2 * rp][6], p[2 * rp + 1][6]);
            w3.y = packpair(p[2 * rp][7], p[2 * rp + 1][7]);
            ulonglong2* dst = (ulonglong2*)(Pp + (ty * 4 + rp) * PP_STRIDE + tx * 8);
            dst[0] = w0;  dst[1] = w1;  dst[2] = w2;  dst[3] = w3;
        }
        __syncwarp();   // P rows (ty*4..+3) are written/read within the same warp

        // ---- PV: out += P @ V  (j unrolled by 2: P loads as ulonglong2) ----
        const float* VsT = Vs + tx * 8;
        const u64*   PpT = Pp + (ty * 4) * PP_STRIDE;
        #pragma unroll 2
        for (int j = 0; j < 64; j += 2) {
            ulonglong2 pA2 = *(const ulonglong2*)&PpT[j];
            ulonglong2 pB2 = *(const ulonglong2*)&PpT[PP_STRIDE + j];
            ulonglong2 pC2 = *(const ulonglong2*)&PpT[2 * PP_STRIDE + j];
            ulonglong2 pD2 = *(const ulonglong2*)&PpT[3 * PP_STRIDE + j];

            float4 va = *(const float4*)(VsT + j * KS_STRIDE);
            float4 vb = *(const float4*)(VsT + j * KS_STRIDE + 4);
            u64 v0 = pack2(va.x), v1 = pack2(va.y), v2 = pack2(va.z), v3 = pack2(va.w);
            u64 v4 = pack2(vb.x), v5 = pack2(vb.y), v6 = pack2(vb.z), v7 = pack2(vb.w);
            acc2[0][0] = ffma2(pA2.x, v0, acc2[0][0]);  acc2[0][1] = ffma2(pA2.x, v1, acc2[0][1]);
            acc2[0][2] = ffma2(pA2.x, v2, acc2[0][2]);  acc2[0][3] = ffma2(pA2.x, v3, acc2[0][3]);
            acc2[0][4] = ffma2(pA2.x, v4, acc2[0][4]);  acc2[0][5] = ffma2(pA2.x, v5, acc2[0][5]);
            acc2[0][6] = ffma2(pA2.x, v6, acc2[0][6]);  acc2[0][7] = ffma2(pA2.x, v7, acc2[0][7]);
            acc2[1][0] = ffma2(pB2.x, v0, acc2[1][0]);  acc2[1][1] = ffma2(pB2.x, v1, acc2[1][1]);
            acc2[1][2] = ffma2(pB2.x, v2, acc2[1][2]);  acc2[1][3] = ffma2(pB2.x, v3, acc2[1][3]);
            acc2[1][4] = ffma2(pB2.x, v4, acc2[1][4]);  acc2[1][5] = ffma2(pB2.x, v5, acc2[1][5]);
            acc2[1][6] = ffma2(pB2.x, v6, acc2[1][6]);  acc2[1][7] = ffma2(pB2.x, v7, acc2[1][7]);
            acc2[2][0] = ffma2(pC2.x, v0, acc2[2][0]);  acc2[2][1] = ffma2(pC2.x, v1, acc2[2][1]);
            acc2[2][2] = ffma2(pC2.x, v2, acc2[2][2]);  acc2[2][3] = ffma2(pC2.x, v3, acc2[2][3]);
            acc2[2][4] = ffma2(pC2.x, v4, acc2[2][4]);  acc2[2][5] = ffma2(pC2.x, v5, acc2[2][5]);
            acc2[2][6] = ffma2(pC2.x, v6, acc2[2][6]);  acc2[2][7] = ffma2(pC2.x, v7, acc2[2][7]);
            acc2[3][0] = ffma2(pD2.x, v0, acc2[3][0]);  acc2[3][1] = ffma2(pD2.x, v1, acc2[3][1]);
            acc2[3][2] = ffma2(pD2.x, v2, acc2[3][2]);  acc2[3][3] = ffma2(pD2.x, v3, acc2[3][3]);
            acc2[3][4] = ffma2(pD2.x, v4, acc2[3][4]);  acc2[3][5] = ffma2(pD2.x, v5, acc2[3][5]);
            acc2[3][6] = ffma2(pD2.x, v6, acc2[3][6]);  acc2[3][7] = ffma2(pD2.x, v7, acc2[3][7]);

            float4 vc = *(const float4*)(VsT + (j + 1) * KS_STRIDE);
            float4 vd = *(const float4*)(VsT + (j + 1) * KS_STRIDE + 4);
            v0 = pack2(vc.x); v1 = pack2(vc.y); v2 = pack2(vc.z); v3 = pack2(vc.w);
            v4 = pack2(vd.x); v5 = pack2(vd.y); v6 = pack2(vd.z); v7 = pack2(vd.w);
            acc2[0][0] = ffma2(pA2.y, v0, acc2[0][0]);  acc2[0][1] = ffma2(pA2.y, v1, acc2[0][1]);
            acc2[0][2] = ffma2(pA2.y, v2, acc2[0][2]);  acc2[0][3] = ffma2(pA2.y, v3, acc2[0][3]);
            acc2[0][4] = ffma2(pA2.y, v4, acc2[0][4]);  acc2[0][5] = ffma2(pA2.y, v5, acc2[0][5]);
            acc2[0][6] = ffma2(pA2.y, v6, acc2[0][6]);  acc2[0][7] = ffma2(pA2.y, v7, acc2[0][7]);
            acc2[1][0] = ffma2(pB2.y, v0, acc2[1][0]);  acc2[1][1] = ffma2(pB2.y, v1, acc2[1][1]);
            acc2[1][2] = ffma2(pB2.y, v2, acc2[1][2]);  acc2[1][3] = ffma2(pB2.y, v3, acc2[1][3]);
            acc2[1][4] = ffma2(pB2.y, v4, acc2[1][4]);  acc2[1][5] = ffma2(pB2.y, v5, acc2[1][5]);
            acc2[1][6] = ffma2(pB2.y, v6, acc2[1][6]);  acc2[1][7] = ffma2(pB2.y, v7, acc2[1][7]);
            acc2[2][0] = ffma2(pC2.y, v0, acc2[2][0]);  acc2[2][1] = ffma2(pC2.y, v1, acc2[2][1]);
            acc2[2][2] = ffma2(pC2.y, v2, acc2[2][2]);  acc2[2][3] = ffma2(pC2.y, v3, acc2[2][3]);
            acc2[2][4] = ffma2(pC2.y, v4, acc2[2][4]);  acc2[2][5] = ffma2(pC2.y, v5, acc2[2][5]);
            acc2[2][6] = ffma2(pC2.y, v6, acc2[2][6]);  acc2[2][7] = ffma2(pC2.y, v7, acc2[2][7]);
            acc2[3][0] = ffma2(pD2.y, v0, acc2[3][0]);  acc2[3][1] = ffma2(pD2.y, v1, acc2[3][1]);
            acc2[3][2] = ffma2(pD2.y, v2, acc2[3][2]);  acc2[3][3] = ffma2(pD2.y, v3, acc2[3][3]);
            acc2[3][4] = ffma2(pD2.y, v4, acc2[3][4]);  acc2[3][5] = ffma2(pD2.y, v5, acc2[3][5]);
            acc2[3][6] = ffma2(pD2.y, v6, acc2[3][6]);  acc2[3][7] = ffma2(pD2.y, v7, acc2[3][7]);
        }
    }

    // ---- epilogue: normalize and write ----
    #pragma unroll
    for (int rp = 0; rp < 4; rp++) {
        const float inv0 = 1.f / l[2 * rp];
        const float inv1 = 1.f / l[2 * rp + 1];
        float o0[8], o1[8];
        #pragma unroll
        for (int c = 0; c < 8; c++) {
            float2 v = unpack2(acc2[rp][c]);
            o0[c] = v.x * inv0;
            o1[c] = v.y * inv1;
        }
        const size_t row0 = (size_t)(b * SS + qt * QT + ty * 8 + 2 * rp);
        float* dst0 = g_att + row0 * DD + h * DK + tx * 8;
        *(float4*)dst0            = make_float4(o0[0], o0[1], o0[2], o0[3]);
        *(float4*)(dst0 + 4)      = make_float4(o0[4], o0[5], o0[6], o0[7]);
        *(float4*)(dst0 + DD)     = make_float4(o1[0], o1[1], o1[2], o1[3]);
        *(float4*)(dst0 + DD + 4) = make_float4(o1[4], o1[5], o1[6], o1[7]);
    }
}

// ---------------------------------------------------------------------------
// Launch
// ---------------------------------------------------------------------------
extern "C" void kernel_launch(void* const* d_in, const int* in_sizes, int n_in,
                              void* d_out, int out_size)
{
    const float* x  = (const float*)d_in[0];
    const float* Wq = (const float*)d_in[1];
    const float* bq = (const float*)d_in[2];
    const float* Wk = (const float*)d_in[3];
    const float* bk = (const float*)d_in[4];
    const float* Wv = (const float*)d_in[5];
    const float* bv = (const float*)d_in[6];
    const float* Wo = (const float*)d_in[7];
    const float* bo = (const float*)d_in[8];
    float* out = (float*)d_out;

    dim3 ggrid(DD / 128, MM / 64);   // (4, 128)

    gemm_bias_kernel<<<ggrid, 256>>>(x, Wq, bq, nullptr, 0);
    gemm_bias_kernel<<<ggrid, 256>>>(x, Wk, bk, nullptr, 1);
    gemm_bias_kernel<<<ggrid, 256>>>(x, Wv, bv, nullptr, 2);

    cudaFuncSetAttribute(attn_kernel,
                         cudaFuncAttributeMaxDynamicSharedMemorySize,
                         SMEM_ATTN);
    attn_kernel<<<dim3(SS / QT, HH, BB), 128, SMEM_ATTN>>>();

    gemm_bias_kernel<<<ggrid, 256>>>(nullptr, Wo, bo, out, 3);
}